// round 1
// baseline (speedup 1.0000x reference)
#include <cuda_runtime.h>
#include <cstddef>

// Problem constants (fixed by the dataset)
#define MAXN 50000
#define HDIM 128
#define ODIM 64

// -------------------- scratch (no allocations allowed) --------------------
__device__ float    g_h[(size_t)MAXN * HDIM];   // fl gemm out / MLP temp
__device__ float    g_B[(size_t)MAXN * HDIM];
__device__ float    g_C[(size_t)MAXN * HDIM];
__device__ float    g_d[MAXN];                  // per-node attention score
__device__ unsigned g_mo[MAXN];                 // ordered-uint max
__device__ float    g_m[MAXN];                  // segment max (float)
__device__ float    g_s[MAXN];                  // segment expsum

// -------------------- helpers --------------------
__device__ __forceinline__ float leaky(float x) { return x > 0.f ? x : 0.2f * x; }

__device__ __forceinline__ unsigned ford(float f) {
    unsigned u = __float_as_uint(f);
    return (u & 0x80000000u) ? ~u : (u | 0x80000000u);
}
__device__ __forceinline__ float funord(unsigned o) {
    return (o & 0x80000000u) ? __uint_as_float(o & 0x7fffffffu) : __uint_as_float(~o);
}

__device__ __forceinline__ void red_add_v4(float* p, float a, float b, float c, float d) {
    asm volatile("red.global.add.v4.f32 [%0], {%1,%2,%3,%4};"
                 :: "l"(p), "f"(a), "f"(b), "f"(c), "f"(d) : "memory");
}

// -------------------- GEMM: C[M,BN] = A[M,128] @ W[BN,128]^T + bias --------------------
// BM=64, BK=16, TM=4; threads=256 (requires BN/TN == 16)
template<int BN, int TN, bool RELU>
__global__ __launch_bounds__(256) void gemm_kernel(
    const float* __restrict__ A, const float* __restrict__ W,
    const float* __restrict__ bias, float* __restrict__ C, int M)
{
    constexpr int BM = 64, BK = 16, TM = 4;
    __shared__ __align__(16) float As[BK][BM];
    __shared__ __align__(16) float Ws[BK][BN];

    const int tid  = threadIdx.x;
    const int tr   = tid >> 4;          // 0..15
    const int tc   = tid & 15;          // 0..15
    const int row0 = blockIdx.x * BM;

    float acc[TM][TN];
    #pragma unroll
    for (int i = 0; i < TM; i++)
        #pragma unroll
        for (int j = 0; j < TN; j++) acc[i][j] = 0.f;

    const int ar = tid >> 2, akg = tid & 3;

    for (int k0 = 0; k0 < 128; k0 += BK) {
        // load A tile (64x16), store transposed As[k][m]
        {
            int grow = row0 + ar;
            float4 a4 = make_float4(0.f, 0.f, 0.f, 0.f);
            if (grow < M)
                a4 = *(const float4*)(A + (size_t)grow * 128 + k0 + akg * 4);
            As[akg * 4 + 0][ar] = a4.x;
            As[akg * 4 + 1][ar] = a4.y;
            As[akg * 4 + 2][ar] = a4.z;
            As[akg * 4 + 3][ar] = a4.w;
        }
        // load W tile (BN x 16), store Ws[k][n]
        #pragma unroll
        for (int i = 0; i < (BN * BK) / (256 * 4); i++) {
            int idx = tid + i * 256;
            int wn = idx >> 2, wkg = idx & 3;
            float4 w4 = *(const float4*)(W + (size_t)wn * 128 + k0 + wkg * 4);
            Ws[wkg * 4 + 0][wn] = w4.x;
            Ws[wkg * 4 + 1][wn] = w4.y;
            Ws[wkg * 4 + 2][wn] = w4.z;
            Ws[wkg * 4 + 3][wn] = w4.w;
        }
        __syncthreads();

        #pragma unroll
        for (int k = 0; k < BK; k++) {
            float4 a = *(const float4*)&As[k][tr * 4];
            float av[4] = {a.x, a.y, a.z, a.w};
            float wv[TN];
            #pragma unroll
            for (int c = 0; c < TN / 4; c++) {
                float4 w = *(const float4*)&Ws[k][tc * TN + c * 4];
                wv[c * 4 + 0] = w.x; wv[c * 4 + 1] = w.y;
                wv[c * 4 + 2] = w.z; wv[c * 4 + 3] = w.w;
            }
            #pragma unroll
            for (int tm = 0; tm < TM; tm++)
                #pragma unroll
                for (int tn = 0; tn < TN; tn++)
                    acc[tm][tn] = fmaf(av[tm], wv[tn], acc[tm][tn]);
        }
        __syncthreads();
    }

    float bv[TN];
    #pragma unroll
    for (int tn = 0; tn < TN; tn++) bv[tn] = bias[tc * TN + tn];

    #pragma unroll
    for (int tm = 0; tm < TM; tm++) {
        int grow = row0 + tr * 4 + tm;
        if (grow >= M) continue;
        #pragma unroll
        for (int c = 0; c < TN / 4; c++) {
            float4 o;
            o.x = acc[tm][c * 4 + 0] + bv[c * 4 + 0];
            o.y = acc[tm][c * 4 + 1] + bv[c * 4 + 1];
            o.z = acc[tm][c * 4 + 2] + bv[c * 4 + 2];
            o.w = acc[tm][c * 4 + 3] + bv[c * 4 + 3];
            if (RELU) {
                o.x = fmaxf(o.x, 0.f); o.y = fmaxf(o.y, 0.f);
                o.z = fmaxf(o.z, 0.f); o.w = fmaxf(o.w, 0.f);
            }
            *(float4*)(C + (size_t)grow * BN + tc * TN + c * 4) = o;
        }
    }
}

// -------------------- attention scalar kernels --------------------
// warp per node: d[i] = h[i] . att ; init mo[i] = ordered(leaky(d[i])) (self loop)
__global__ void node_score_kernel(const float* __restrict__ h,
                                  const float* __restrict__ att, int n)
{
    int gw = (blockIdx.x * blockDim.x + threadIdx.x) >> 5;
    int lane = threadIdx.x & 31;
    if (gw >= n) return;
    float4 hv = *(const float4*)(h + (size_t)gw * 128 + lane * 4);
    float4 av = *(const float4*)(att + lane * 4);
    float p = hv.x * av.x + hv.y * av.y + hv.z * av.z + hv.w * av.w;
    #pragma unroll
    for (int o = 16; o; o >>= 1) p += __shfl_xor_sync(0xffffffffu, p, o);
    if (lane == 0) {
        g_d[gw]  = p;
        g_mo[gw] = ford(leaky(p));
    }
}

__global__ void edge_max_kernel(const int* __restrict__ row, int E)
{
    int e = blockIdx.x * blockDim.x + threadIdx.x;
    if (e >= E) return;
    int r = row[e];
    atomicMax(&g_mo[r], ford(leaky(g_d[r])));
}

__global__ void node_fin_kernel(int n)
{
    int i = blockIdx.x * blockDim.x + threadIdx.x;
    if (i >= n) return;
    float m = funord(g_mo[i]);
    g_m[i] = m;
    g_s[i] = expf(leaky(g_d[i]) - m);   // self-loop term
}

__global__ void edge_sum_kernel(const int* __restrict__ row, int E)
{
    int e = blockIdx.x * blockDim.x + threadIdx.x;
    if (e >= E) return;
    int r = row[e];
    atomicAdd(&g_s[r], expf(leaky(g_d[r]) - g_m[r]));
}

// self-loop message: B[i] = coef_self(i) * h[i]
__global__ void self_msg_kernel(int n)
{
    int idx = blockIdx.x * blockDim.x + threadIdx.x;
    if (idx >= n * 32) return;
    int i = idx >> 5;
    float coef = expf(leaky(g_d[i]) - g_m[i]) / g_s[i];
    float4 v = *(const float4*)(g_h + (size_t)i * 128 + (idx & 31) * 4);
    v.x *= coef; v.y *= coef; v.z *= coef; v.w *= coef;
    *(float4*)(g_B + (size_t)i * 128 + (idx & 31) * 4) = v;
}

// warp per edge: B[col] += coef(row) * h[row]
__global__ void edge_msg_kernel(const int* __restrict__ row,
                                const int* __restrict__ col, int E)
{
    int e = (blockIdx.x * blockDim.x + threadIdx.x) >> 5;
    int lane = threadIdx.x & 31;
    if (e >= E) return;
    int r = row[e], c = col[e];
    float coef = expf(leaky(g_d[r]) - g_m[r]) / g_s[r];
    float4 v = *(const float4*)(g_h + (size_t)r * 128 + lane * 4);
    red_add_v4(g_B + (size_t)c * 128 + lane * 4,
               coef * v.x, coef * v.y, coef * v.z, coef * v.w);
}

// warp per edge: dst[col] += src[row]  (GIN aggregation)
__global__ void edge_agg_kernel(const int* __restrict__ row,
                                const int* __restrict__ col,
                                const float* __restrict__ src,
                                float* __restrict__ dst, int E)
{
    int e = (blockIdx.x * blockDim.x + threadIdx.x) >> 5;
    int lane = threadIdx.x & 31;
    if (e >= E) return;
    int r = row[e], c = col[e];
    float4 v = *(const float4*)(src + (size_t)r * 128 + lane * 4);
    red_add_v4(dst + (size_t)c * 128 + lane * 4, v.x, v.y, v.z, v.w);
}

__global__ void relu_kernel(float* __restrict__ x, size_t n4)
{
    size_t i = (size_t)blockIdx.x * blockDim.x + threadIdx.x;
    if (i >= n4) return;
    float4 v = *(float4*)(x + i * 4);
    v.x = fmaxf(v.x, 0.f); v.y = fmaxf(v.y, 0.f);
    v.z = fmaxf(v.z, 0.f); v.w = fmaxf(v.w, 0.f);
    *(float4*)(x + i * 4) = v;
}

__global__ void copy_kernel(float* __restrict__ dst, const float* __restrict__ src, size_t n4)
{
    size_t i = (size_t)blockIdx.x * blockDim.x + threadIdx.x;
    if (i >= n4) return;
    *(float4*)(dst + i * 4) = *(const float4*)(src + i * 4);
}

// warp per row, 64 cols: in-place log_softmax
__global__ void lsm_kernel(float* __restrict__ out, int n)
{
    int r = (blockIdx.x * blockDim.x + threadIdx.x) >> 5;
    int lane = threadIdx.x & 31;
    if (r >= n) return;
    float x0 = out[(size_t)r * 64 + lane];
    float x1 = out[(size_t)r * 64 + 32 + lane];
    float m = fmaxf(x0, x1);
    #pragma unroll
    for (int o = 16; o; o >>= 1) m = fmaxf(m, __shfl_xor_sync(0xffffffffu, m, o));
    float s = expf(x0 - m) + expf(x1 - m);
    #pragma unroll
    for (int o = 16; o; o >>= 1) s += __shfl_xor_sync(0xffffffffu, s, o);
    float ls = logf(s) + m;
    out[(size_t)r * 64 + lane]      = x0 - ls;
    out[(size_t)r * 64 + 32 + lane] = x1 - ls;
}

// -------------------- launch --------------------
extern "C" void kernel_launch(void* const* d_in, const int* in_sizes, int n_in,
                              void* d_out, int out_size)
{
    const float* x      = (const float*)d_in[0];
    const int*   ei     = (const int*)  d_in[1];
    const float* fl_W   = (const float*)d_in[2];
    const float* fl_b   = (const float*)d_in[3];
    const float* fl_att = (const float*)d_in[4];
    const float* g1_W1  = (const float*)d_in[5];
    const float* g1_b1  = (const float*)d_in[6];
    const float* g1_W2  = (const float*)d_in[7];
    const float* g1_b2  = (const float*)d_in[8];
    const float* g2_W1  = (const float*)d_in[9];
    const float* g2_b1  = (const float*)d_in[10];
    const float* g2_W2  = (const float*)d_in[11];
    const float* g2_b2  = (const float*)d_in[12];
    const float* out_W  = (const float*)d_in[13];
    const float* out_b  = (const float*)d_in[14];
    float* out = (float*)d_out;

    const int N = in_sizes[0] / HDIM;
    const int E = in_sizes[1] / 2;
    const int* row = ei;
    const int* col = ei + E;

    float *pH = nullptr, *pB = nullptr, *pC = nullptr;
    cudaGetSymbolAddress((void**)&pH, g_h);
    cudaGetSymbolAddress((void**)&pB, g_B);
    cudaGetSymbolAddress((void**)&pC, g_C);

    const int T = 256;
    const int gemmGrid   = (N + 63) / 64;
    const int edgeWarpG  = (E * 32 + T - 1) / T;   // warp-per-edge kernels
    const int edgeThG    = (E + T - 1) / T;        // thread-per-edge kernels
    const int nodeWarpG  = (N * 32 + T - 1) / T;   // warp-per-node kernels
    const int nodeThG    = (N + T - 1) / T;
    const size_t n4      = (size_t)N * 32;         // float4 count per feature buffer
    const int vecG       = (int)((n4 + T - 1) / T);

    // 1. h = x @ fl_W^T + fl_b
    gemm_kernel<128, 8, false><<<gemmGrid, T>>>(x, fl_W, fl_b, pH, N);
    // 2-5. attention scalars (softmax grouped by source node, self loops included)
    node_score_kernel<<<nodeWarpG, T>>>(pH, fl_att, N);
    edge_max_kernel<<<edgeThG, T>>>(row, E);
    node_fin_kernel<<<nodeThG, T>>>(N);
    edge_sum_kernel<<<edgeThG, T>>>(row, E);
    // 6-8. weighted aggregation into B, then ReLU -> h1
    self_msg_kernel<<<nodeWarpG, T>>>(N);
    edge_msg_kernel<<<edgeWarpG, T>>>(row, col, E);
    relu_kernel<<<vecG, T>>>(pB, n4);
    // 9-12. GIN layer 1: z = h1 + agg(h1); h2 = relu(relu(z@W1^T+b1)@W2^T+b2)
    copy_kernel<<<vecG, T>>>(pC, pB, n4);
    edge_agg_kernel<<<edgeWarpG, T>>>(row, col, pB, pC, E);
    gemm_kernel<128, 8, true><<<gemmGrid, T>>>(pC, g1_W1, g1_b1, pH, N);
    gemm_kernel<128, 8, true><<<gemmGrid, T>>>(pH, g1_W2, g1_b2, pC, N);
    // 13-16. GIN layer 2
    copy_kernel<<<vecG, T>>>(pB, pC, n4);
    edge_agg_kernel<<<edgeWarpG, T>>>(row, col, pC, pB, E);
    gemm_kernel<128, 8, true><<<gemmGrid, T>>>(pB, g2_W1, g2_b1, pH, N);
    gemm_kernel<128, 8, true><<<gemmGrid, T>>>(pH, g2_W2, g2_b2, pB, N);
    // 17-18. output head + log_softmax
    gemm_kernel<64, 4, false><<<gemmGrid, T>>>(pB, out_W, out_b, out, N);
    lsm_kernel<<<nodeWarpG, T>>>(out, N);
}